// round 14
// baseline (speedup 1.0000x reference)
#include <cuda_runtime.h>
#include <cstdint>

#define CDIM 192
#define NHEADS 6
#define HDIM 32
#define NTOK 49
#define NWIN 4096
#define MROWS 200704
#define HID 768
#define QKSCALE 0.17677669529663687f

// ---------------- scratch buffers (static device memory; no allocs) --------
__device__ __align__(128) float g_win[(size_t)MROWS * CDIM];
__device__ __align__(128) float g_qkv[(size_t)MROWS * (3 * CDIM)];
__device__ __align__(128) float g_att[(size_t)MROWS * CDIM];
__device__ __align__(128) float g_x1[(size_t)MROWS * CDIM];
__device__ __align__(128) float g_y[(size_t)MROWS * CDIM];
__device__ __align__(128) float g_h1[(size_t)MROWS * HID];
__device__ __align__(128) float g_x0[(size_t)MROWS * CDIM];

__device__ __forceinline__ int map_row(int m, int shift) {
    int w = m / NTOK;
    int n = m - w * NTOK;
    int b = w >> 6;
    int widx = w & 63;
    int wy = widx >> 3, wx = widx & 7;
    int ty = n / 7, tx = n - ty * 7;
    int sy = wy * 7 + ty + shift; if (sy >= 56) sy -= 56;
    int sx = wx * 7 + tx + shift; if (sx >= 56) sx -= 56;
    return b * 3136 + sy * 56 + sx;
}

// ---------------- LayerNorm kernels ----------------------------------------
__global__ void ln_part_kernel(const float* __restrict__ x,
                               const float* __restrict__ gw,
                               const float* __restrict__ gb,
                               float* __restrict__ out, int shift)
{
    int t = blockIdx.x;
    int src = map_row(t, shift);
    int c = threadIdx.x;
    float v = x[(size_t)src * CDIM + c];
    __shared__ float sb[12];
    float s = v, s2 = v * v;
    #pragma unroll
    for (int o = 16; o; o >>= 1) {
        s  += __shfl_xor_sync(0xffffffffu, s, o);
        s2 += __shfl_xor_sync(0xffffffffu, s2, o);
    }
    int warp = c >> 5;
    if ((c & 31) == 0) { sb[warp] = s; sb[warp + 6] = s2; }
    __syncthreads();
    float ts = 0.f, ts2 = 0.f;
    #pragma unroll
    for (int i = 0; i < 6; i++) { ts += sb[i]; ts2 += sb[i + 6]; }
    float mu  = ts  * (1.0f / CDIM);
    float var = ts2 * (1.0f / CDIM) - mu * mu;
    float inv = rsqrtf(var + 1e-5f);
    out[(size_t)t * CDIM + c] = (v - mu) * inv * gw[c] + gb[c];
}

__global__ void ln_kernel(const float* __restrict__ x,
                          const float* __restrict__ gw,
                          const float* __restrict__ gb,
                          float* __restrict__ out)
{
    int t = blockIdx.x;
    int c = threadIdx.x;
    float v = x[(size_t)t * CDIM + c];
    __shared__ float sb[12];
    float s = v, s2 = v * v;
    #pragma unroll
    for (int o = 16; o; o >>= 1) {
        s  += __shfl_xor_sync(0xffffffffu, s, o);
        s2 += __shfl_xor_sync(0xffffffffu, s2, o);
    }
    int warp = c >> 5;
    if ((c & 31) == 0) { sb[warp] = s; sb[warp + 6] = s2; }
    __syncthreads();
    float ts = 0.f, ts2 = 0.f;
    #pragma unroll
    for (int i = 0; i < 6; i++) { ts += sb[i]; ts2 += sb[i + 6]; }
    float mu  = ts  * (1.0f / CDIM);
    float var = ts2 * (1.0f / CDIM) - mu * mu;
    float inv = rsqrtf(var + 1e-5f);
    out[(size_t)t * CDIM + c] = (v - mu) * inv * gw[c] + gb[c];
}

// ---------------- windowed attention (fp32, float4 smem paths) -------------
__global__ void __launch_bounds__(256)
attn_kernel(const float* __restrict__ qkv, const float* __restrict__ rpb,
            float* __restrict__ out, int shift)
{
    __shared__ __align__(16) float Q[NTOK][36], Kt[NTOK][36], V[NTOK][36];
    __shared__ float S[NTOK][52];
    __shared__ int reg[NTOK];
    int w = blockIdx.x;
    int h = blockIdx.y;
    int tid = threadIdx.x;
    int widx = w & 63;
    int wy = widx >> 3, wx = widx & 7;

    for (int idx = tid; idx < NTOK * 8; idx += 256) {
        int n = idx >> 3, d4 = idx & 7;
        const float4* p = (const float4*)(qkv + (size_t)(w * NTOK + n) * (3 * CDIM)
                                          + h * HDIM + (d4 << 2));
        *(float4*)&Q[n][d4 << 2]  = p[0];
        *(float4*)&Kt[n][d4 << 2] = p[CDIM / 4];
        *(float4*)&V[n][d4 << 2]  = p[2 * CDIM / 4];
    }
    if (shift && tid < NTOK) {
        int ty = tid / 7, tx = tid - ty * 7;
        int sy = wy * 7 + ty, sx = wx * 7 + tx;
        int ry = (sy < 49) ? 0 : ((sy < 53) ? 1 : 2);
        int rx = (sx < 49) ? 0 : ((sx < 53) ? 1 : 2);
        reg[tid] = ry * 3 + rx;
    }
    __syncthreads();

    for (int idx = tid; idx < NTOK * NTOK; idx += 256) {
        int i = idx / NTOK, j = idx - i * NTOK;
        float4 a = make_float4(0.f, 0.f, 0.f, 0.f);
        #pragma unroll
        for (int d4 = 0; d4 < 8; d4++) {
            float4 q = *(const float4*)&Q[i][d4 << 2];
            float4 k = *(const float4*)&Kt[j][d4 << 2];
            a.x = fmaf(q.x, k.x, a.x); a.y = fmaf(q.y, k.y, a.y);
            a.z = fmaf(q.z, k.z, a.z); a.w = fmaf(q.w, k.w, a.w);
        }
        float s = (a.x + a.y) + (a.z + a.w);
        int yi = i / 7, xi = i - yi * 7;
        int yj = j / 7, xj = j - yj * 7;
        int ridx = (yi - yj + 6) * 13 + (xi - xj + 6);
        s = s * QKSCALE + __ldg(&rpb[ridx * NHEADS + h]);
        if (shift && reg[i] != reg[j]) s -= 100.f;
        S[i][j] = s;
    }
    __syncthreads();

    int warp = tid >> 5, lane = tid & 31;
    for (int i = warp; i < NTOK; i += 8) {
        float m = -1e30f;
        for (int j = lane; j < NTOK; j += 32) m = fmaxf(m, S[i][j]);
        #pragma unroll
        for (int o = 16; o; o >>= 1) m = fmaxf(m, __shfl_xor_sync(0xffffffffu, m, o));
        float sum = 0.f;
        for (int j = lane; j < NTOK; j += 32) {
            float e = __expf(S[i][j] - m); S[i][j] = e; sum += e;
        }
        #pragma unroll
        for (int o = 16; o; o >>= 1) sum += __shfl_xor_sync(0xffffffffu, sum, o);
        float inv = 1.f / sum;
        for (int j = lane; j < NTOK; j += 32) S[i][j] *= inv;
    }
    __syncthreads();

    for (int idx = tid; idx < NTOK * 8; idx += 256) {
        int i = idx >> 3, d4 = idx & 7;
        float4 o = make_float4(0.f, 0.f, 0.f, 0.f);
        #pragma unroll 7
        for (int j = 0; j < NTOK; j++) {
            float s = S[i][j];
            float4 v = *(const float4*)&V[j][d4 << 2];
            o.x = fmaf(s, v.x, o.x); o.y = fmaf(s, v.y, o.y);
            o.z = fmaf(s, v.z, o.z); o.w = fmaf(s, v.w, o.w);
        }
        *(float4*)&out[(size_t)(w * NTOK + i) * CDIM + h * HDIM + (d4 << 2)] = o;
    }
}

// ---------------- tf32 tensor-core GEMM, CTA tile 128x96 -------------------
// C[M,N] = A[M,K] @ B[K,N] + bias. 256 threads, 8 warps (4m x 2n),
// warp tile 32x48 = 12 independent m16n8k8 MMAs per k8 step.
// cp.async 3-stage, one __syncthreads per K-iter, dynamic smem.
// EPI: 0 = bias, 1 = bias+GELU, 2 = bias+residual, 3 = bias+scatter+residual.

__device__ __forceinline__ float gelu_f(float v) {
    return 0.5f * v * (1.f + erff(v * 0.7071067811865476f));
}

#define ASTRIDE 20
#define BSTRIDE 104
#define NTILE 96
#define STAGES 3
#define A_FLOATS (128 * ASTRIDE)
#define B_FLOATS (16 * BSTRIDE)
#define SMEM_GEMM (STAGES * (A_FLOATS + B_FLOATS) * 4)

__device__ __forceinline__ void cp16(uint32_t dst, const float* src) {
    asm volatile("cp.async.cg.shared.global [%0], [%1], 16;\n" :: "r"(dst), "l"(src));
}

template<int EPI>
__global__ void __launch_bounds__(256, 2)
tgemm_kernel(const float* __restrict__ A, const float* __restrict__ Bw,
             const float* __restrict__ bias, const float* __restrict__ res,
             float* __restrict__ C, int K, int N, int shift)
{
    extern __shared__ __align__(16) float sm[];
    // layout: [STAGES][A_FLOATS] then [STAGES][B_FLOATS]
    float* Abase = sm;
    float* Bbase = sm + STAGES * A_FLOATS;

    int tid  = threadIdx.x;
    int wid  = tid >> 5;
    int lane = tid & 31;
    int wm = (wid & 3) << 5;        // warp row offset 0,32,64,96
    int wn = (wid >> 2) * 48;       // warp col offset 0/48
    int row0 = blockIdx.y << 7;
    int col0 = blockIdx.x * NTILE;

    // A loader: rows ar, ar+64; k piece aq
    int ar = tid >> 2;
    int aq = (tid & 3) << 2;
    const float* Ap = A + (size_t)(row0 + ar) * K + aq;

    // B loader: 384 float4 items (16 rows x 24), items tid and tid+256
    int it0_r = tid / 24,          it0_c = (tid % 24) << 2;
    int it1   = tid + 256;
    int it1_r = it1 / 24,          it1_c = (it1 % 24) << 2;
    bool has1 = it1 < 384;
    const float* Bp0 = Bw + (size_t)it0_r * N + col0 + it0_c;
    const float* Bp1 = Bw + (size_t)it1_r * N + col0 + it1_c;

    uint32_t sA[STAGES], sB0[STAGES], sB1[STAGES];
    #pragma unroll
    for (int b = 0; b < STAGES; b++) {
        sA[b]  = (uint32_t)__cvta_generic_to_shared(Abase + b * A_FLOATS + ar * ASTRIDE + aq);
        sB0[b] = (uint32_t)__cvta_generic_to_shared(Bbase + b * B_FLOATS + it0_r * BSTRIDE + it0_c);
        sB1[b] = (uint32_t)__cvta_generic_to_shared(Bbase + b * B_FLOATS + it1_r * BSTRIDE + it1_c);
    }
    const uint32_t aRowStep = 64u * ASTRIDE * 4u;

    float acc[2][6][4];
    #pragma unroll
    for (int mt = 0; mt < 2; mt++)
        #pragma unroll
        for (int nt = 0; nt < 6; nt++)
            #pragma unroll
            for (int i = 0; i < 4; i++) acc[mt][nt][i] = 0.f;

    // ldmatrix addressing (A fragments)
    int lrow = lane & 7;
    int seg  = lane >> 3;
    int arow = wm + ((seg & 1) << 3) + lrow;
    int acol = (seg >> 1) << 2;

    int nIter = K >> 4;

    #define STAGE_LD(s_, k0_) do {                                            \
        cp16(sA[s_],            Ap + (k0_));                                   \
        cp16(sA[s_] + aRowStep, Ap + (size_t)64 * K + (k0_));                  \
        cp16(sB0[s_],           Bp0 + (size_t)(k0_) * N);                      \
        if (has1) cp16(sB1[s_], Bp1 + (size_t)(k0_) * N);                      \
        asm volatile("cp.async.commit_group;\n");                              \
    } while (0)

    STAGE_LD(0, 0);
    STAGE_LD(1, 16);

    for (int it = 0; it < nIter; it++) {
        int buf = it % STAGES;
        if (it + 1 < nIter) asm volatile("cp.async.wait_group 1;\n");
        else                asm volatile("cp.async.wait_group 0;\n");
        __syncthreads();
        if (it + 2 < nIter) {
            int nb = (it + 2) % STAGES;
            int k0 = (it + 2) << 4;
            STAGE_LD(nb, k0);
        }
        const float* Ab = Abase + buf * A_FLOATS;
        const float* Bb = Bbase + buf * B_FLOATS;
        #pragma unroll
        for (int kk = 0; kk < 16; kk += 8) {
            uint32_t afr[2][4];
            #pragma unroll
            for (int mt = 0; mt < 2; mt++) {
                uint32_t addr = (uint32_t)__cvta_generic_to_shared(
                    Ab + (arow + (mt << 4)) * ASTRIDE + kk + acol);
                asm volatile(
                    "ldmatrix.sync.aligned.m8n8.x4.shared.b16 {%0,%1,%2,%3}, [%4];\n"
                    : "=r"(afr[mt][0]), "=r"(afr[mt][1]),
                      "=r"(afr[mt][2]), "=r"(afr[mt][3])
                    : "r"(addr));
            }
            uint32_t bfr[6][2];
            int bkr = kk + (lane & 3);
            int bnc = wn + (lane >> 2);
            #pragma unroll
            for (int nt = 0; nt < 6; nt++) {
                bfr[nt][0] = __float_as_uint(Bb[bkr * BSTRIDE + bnc + (nt << 3)]);
                bfr[nt][1] = __float_as_uint(Bb[(bkr + 4) * BSTRIDE + bnc + (nt << 3)]);
            }
            #pragma unroll
            for (int mt = 0; mt < 2; mt++)
                #pragma unroll
                for (int nt = 0; nt < 6; nt++) {
                    asm volatile(
                        "mma.sync.aligned.m16n8k8.row.col.f32.tf32.tf32.f32 "
                        "{%0,%1,%2,%3},{%4,%5,%6,%7},{%8,%9},{%0,%1,%2,%3};\n"
                        : "+f"(acc[mt][nt][0]), "+f"(acc[mt][nt][1]),
                          "+f"(acc[mt][nt][2]), "+f"(acc[mt][nt][3])
                        : "r"(afr[mt][0]), "r"(afr[mt][1]),
                          "r"(afr[mt][2]), "r"(afr[mt][3]),
                          "r"(bfr[nt][0]), "r"(bfr[nt][1]));
                }
        }
    }

    // epilogue
    int erow = (lane >> 2);
    int ecol = (lane & 3) << 1;
    #pragma unroll
    for (int mt = 0; mt < 2; mt++) {
        #pragma unroll
        for (int half = 0; half < 2; half++) {
            int m = row0 + wm + (mt << 4) + erow + (half << 3);
            size_t roff;
            if (EPI == 3) roff = (size_t)map_row(m, shift) * N;
            else          roff = (size_t)m * N;
            #pragma unroll
            for (int nt = 0; nt < 6; nt++) {
                int col = col0 + wn + (nt << 3) + ecol;
                float v0 = acc[mt][nt][half * 2 + 0] + __ldg(&bias[col]);
                float v1 = acc[mt][nt][half * 2 + 1] + __ldg(&bias[col + 1]);
                if (EPI == 1) { v0 = gelu_f(v0); v1 = gelu_f(v1); }
                if (EPI == 2 || EPI == 3) {
                    float2 r = *(const float2*)&res[roff + col];
                    v0 += r.x; v1 += r.y;
                }
                float2 o; o.x = v0; o.y = v1;
                *(float2*)&C[roff + col] = o;
            }
        }
    }
}

// ---------------- launcher -------------------------------------------------
extern "C" void kernel_launch(void* const* d_in, const int* in_sizes, int n_in,
                              void* d_out, int out_size)
{
    const float* x     = (const float*)d_in[0];
    const float* ln1g  = (const float*)d_in[1];
    const float* ln1b  = (const float*)d_in[2];
    const float* qkvw  = (const float*)d_in[3];
    const float* qkvb  = (const float*)d_in[4];
    const float* rpb   = (const float*)d_in[5];
    const float* projw = (const float*)d_in[6];
    const float* projb = (const float*)d_in[7];
    const float* ln2g  = (const float*)d_in[8];
    const float* ln2b  = (const float*)d_in[9];
    const float* fc1w  = (const float*)d_in[10];
    const float* fc1b  = (const float*)d_in[11];
    const float* fc2w  = (const float*)d_in[12];
    const float* fc2b  = (const float*)d_in[13];

    float *p_win, *p_qkv, *p_att, *p_x1, *p_y, *p_h1, *p_x0;
    cudaGetSymbolAddress((void**)&p_win, g_win);
    cudaGetSymbolAddress((void**)&p_qkv, g_qkv);
    cudaGetSymbolAddress((void**)&p_att, g_att);
    cudaGetSymbolAddress((void**)&p_x1,  g_x1);
    cudaGetSymbolAddress((void**)&p_y,   g_y);
    cudaGetSymbolAddress((void**)&p_h1,  g_h1);
    cudaGetSymbolAddress((void**)&p_x0,  g_x0);

    static bool attr_set = false;
    if (!attr_set) {
        cudaFuncSetAttribute(tgemm_kernel<0>, cudaFuncAttributeMaxDynamicSharedMemorySize, SMEM_GEMM);
        cudaFuncSetAttribute(tgemm_kernel<1>, cudaFuncAttributeMaxDynamicSharedMemorySize, SMEM_GEMM);
        cudaFuncSetAttribute(tgemm_kernel<2>, cudaFuncAttributeMaxDynamicSharedMemorySize, SMEM_GEMM);
        cudaFuncSetAttribute(tgemm_kernel<3>, cudaFuncAttributeMaxDynamicSharedMemorySize, SMEM_GEMM);
        attr_set = true;
    }

    const int MB = MROWS / 128;   // 1568

    for (int dep = 0; dep < 2; dep++) {
        int shift = dep ? 3 : 0;
        const float* src = dep ? (const float*)p_x0 : x;
        float* dst = dep ? (float*)d_out : p_x0;

        ln_part_kernel<<<MROWS, 192>>>(src, ln1g + dep * CDIM, ln1b + dep * CDIM,
                                       p_win, shift);
        tgemm_kernel<0><<<dim3(6, MB), 256, SMEM_GEMM>>>(p_win,
                    qkvw + (size_t)dep * CDIM * 3 * CDIM,
                    qkvb + dep * 3 * CDIM, nullptr, p_qkv, CDIM, 3 * CDIM, 0);
        attn_kernel<<<dim3(NWIN, NHEADS), 256>>>(p_qkv, rpb + dep * 169 * NHEADS,
                                                 p_att, shift);
        tgemm_kernel<3><<<dim3(2, MB), 256, SMEM_GEMM>>>(p_att,
                    projw + (size_t)dep * CDIM * CDIM,
                    projb + dep * CDIM, src, p_x1, CDIM, CDIM, shift);
        ln_kernel<<<MROWS, 192>>>(p_x1, ln2g + dep * CDIM, ln2b + dep * CDIM, p_y);
        tgemm_kernel<1><<<dim3(8, MB), 256, SMEM_GEMM>>>(p_y,
                    fc1w + (size_t)dep * CDIM * HID,
                    fc1b + dep * HID, nullptr, p_h1, CDIM, HID, 0);
        tgemm_kernel<2><<<dim3(2, MB), 256, SMEM_GEMM>>>(p_h1,
                    fc2w + (size_t)dep * HID * CDIM,
                    fc2b + dep * CDIM, p_x1, dst, HID, CDIM, 0);
    }
}